// round 6
// baseline (speedup 1.0000x reference)
#include <cuda_runtime.h>
#include <cstdint>
#include <cstddef>

#define EXPERTS 8
#define TOK     2048
#define DMODEL  1024
#define HID     4096

// Static device scratch (no allocations allowed anywhere)
__device__ float g_hidden[(size_t)EXPERTS * TOK * HID];   // 256MB, tf32-rounded by kernel1
__device__ float g_x [(size_t)EXPERTS * TOK * DMODEL];    // 64MB, tf32-rounded x
__device__ float g_w1[(size_t)EXPERTS * DMODEL * HID];    // 128MB, tf32-rounded w1
__device__ float g_w2[(size_t)EXPERTS * HID * DMODEL];    // 128MB, tf32-rounded w2

// CTA tile 128x128, 128 threads (4 warps 2x2, 64x64 each), BK=32, 3-stage cp.async
#define BM 128
#define BN 128
#define BK 32
#define APITCH 36      // frag bank = (36*grp+qid)%32 = 4*grp+qid -> all 32 distinct
#define BPITCH 136     // frag bank = (136*qid+grp)%32 = 8*qid+grp -> all 32 distinct
#define A_FLOATS (BM * APITCH)            // 4608
#define B_FLOATS (BK * BPITCH)            // 4352
#define S_FLOATS (A_FLOATS + B_FLOATS)    // 8960 (35840 B/stage)
#define DSMEM_BYTES (3 * S_FLOATS * 4)    // 107520 B -> 2 CTAs/SM (215KB <= 228KB)

static __device__ __forceinline__ uint32_t smem_u32(const void* p) {
    uint32_t a;
    asm("{ .reg .u64 t; cvta.to.shared.u64 t, %1; cvt.u32.u64 %0, t; }" : "=r"(a) : "l"(p));
    return a;
}
static __device__ __forceinline__ void cp16(void* d, const void* s) {
    asm volatile("cp.async.cg.shared.global [%0], [%1], 16;" :: "r"(smem_u32(d)), "l"(s));
}
static __device__ __forceinline__ float4 cvt4(float4 v) {
    uint4 o;
    asm("cvt.rna.tf32.f32 %0, %1;" : "=r"(o.x) : "f"(v.x));
    asm("cvt.rna.tf32.f32 %0, %1;" : "=r"(o.y) : "f"(v.y));
    asm("cvt.rna.tf32.f32 %0, %1;" : "=r"(o.z) : "f"(v.z));
    asm("cvt.rna.tf32.f32 %0, %1;" : "=r"(o.w) : "f"(v.w));
    float4 r;
    r.x = __uint_as_float(o.x); r.y = __uint_as_float(o.y);
    r.z = __uint_as_float(o.z); r.w = __uint_as_float(o.w);
    return r;
}
static __device__ __forceinline__ float cvt1(float v) {
    uint32_t o;
    asm("cvt.rna.tf32.f32 %0, %1;" : "=r"(o) : "f"(v));
    return __uint_as_float(o);
}

// Elementwise tf32-rounding prepass (grid-stride, float4)
__global__ void round_tf32(const float4* __restrict__ in, float4* __restrict__ out, int n4) {
    for (int i = blockIdx.x * blockDim.x + threadIdx.x; i < n4; i += gridDim.x * blockDim.x)
        out[i] = cvt4(in[i]);
}

// C = relu?(A*B + bias) with optional tf32-rounding of the output.
// A[M,K], B[K,N] row-major, PRE-ROUNDED to tf32 grid. Batched over blockIdx.z.
template <bool RELU_ROUND>
__global__ __launch_bounds__(128, 2)
void ffn_gemm(const float* __restrict__ A, const float* __restrict__ B,
              const float* __restrict__ bias, float* __restrict__ C,
              int M, int N, int K)
{
    extern __shared__ __align__(16) float sm[];

    const int e = blockIdx.z;
    const float* Ae = A + (size_t)e * M * K;
    const float* Be = B + (size_t)e * K * N;
    const float* be = bias + (size_t)e * N;
    float*       Ce = C + (size_t)e * M * N;

    const int bm = blockIdx.y * BM;
    const int bn = blockIdx.x * BN;

    const int tid  = threadIdx.x;
    const int warp = tid >> 5;
    const int lane = tid & 31;
    const int wm   = (warp >> 1) * 64;
    const int wn   = (warp & 1) * 64;
    const int grp  = lane >> 2;
    const int qid  = lane & 3;

    float c[4][8][4];
    #pragma unroll
    for (int i = 0; i < 4; i++)
        #pragma unroll
        for (int j = 0; j < 8; j++)
            #pragma unroll
            for (int r = 0; r < 4; r++) c[i][j][r] = 0.f;

    const int nk = K / BK;

    // cp.async loader: A 1024 chunks (128 rows x 8), B 1024 chunks (32 rows x 32); 8+8/thread
    auto issue = [&](int t) {
        const int s = t % 3;
        float* As = sm + s * S_FLOATS;
        float* Bs = As + A_FLOATS;
        const int k0 = t * BK;
        #pragma unroll
        for (int i = 0; i < 8; i++) {
            int f = tid + (i << 7);
            int r = f >> 3, ch = (f & 7) << 2;
            cp16(As + r * APITCH + ch, Ae + (size_t)(bm + r) * K + k0 + ch);
        }
        #pragma unroll
        for (int i = 0; i < 8; i++) {
            int f = tid + (i << 7);
            int r = f >> 5, ch = (f & 31) << 2;
            cp16(Bs + r * BPITCH + ch, Be + (size_t)(k0 + r) * N + bn + ch);
        }
        asm volatile("cp.async.commit_group;" ::: "memory");
    };

    uint32_t fa[2][4][4], fb[2][8][2];
    auto ldfrag = [&](const float* As, const float* Bs, int kk, int buf) {
        #pragma unroll
        for (int i = 0; i < 4; i++) {
            const float* ap = As + (wm + i * 16 + grp) * APITCH + kk + qid;
            fa[buf][i][0] = __float_as_uint(ap[0]);
            fa[buf][i][1] = __float_as_uint(ap[8 * APITCH]);
            fa[buf][i][2] = __float_as_uint(ap[4]);
            fa[buf][i][3] = __float_as_uint(ap[8 * APITCH + 4]);
        }
        #pragma unroll
        for (int j = 0; j < 8; j++) {
            const float* bp = Bs + (kk + qid) * BPITCH + wn + j * 8 + grp;
            fb[buf][j][0] = __float_as_uint(bp[0]);
            fb[buf][j][1] = __float_as_uint(bp[4 * BPITCH]);
        }
    };
    auto domma = [&](int buf) {
        #pragma unroll
        for (int i = 0; i < 4; i++)
            #pragma unroll
            for (int j = 0; j < 8; j++) {
                asm volatile(
                    "mma.sync.aligned.m16n8k8.row.col.f32.tf32.tf32.f32 "
                    "{%0,%1,%2,%3}, {%4,%5,%6,%7}, {%8,%9}, {%0,%1,%2,%3};"
                    : "+f"(c[i][j][0]), "+f"(c[i][j][1]),
                      "+f"(c[i][j][2]), "+f"(c[i][j][3])
                    : "r"(fa[buf][i][0]), "r"(fa[buf][i][1]),
                      "r"(fa[buf][i][2]), "r"(fa[buf][i][3]),
                      "r"(fb[buf][j][0]), "r"(fb[buf][j][1]));
            }
    };

    // Prologue: stages 0 and 1 in flight; wait for 0.
    issue(0);
    issue(1);
    asm volatile("cp.async.wait_group 1;" ::: "memory");
    __syncthreads();

    for (int t = 0; t < nk; t++) {
        if (t + 2 < nk) issue(t + 2);   // stage (t+2)%3 == (t-1)%3, freed by last sync

        const float* As = sm + (t % 3) * S_FLOATS;
        const float* Bs = As + A_FLOATS;

        // 4 kk-slices, fragment double-buffered
        ldfrag(As, Bs, 0, 0);
        #pragma unroll
        for (int s = 0; s < 4; s++) {
            if (s < 3) ldfrag(As, Bs, (s + 1) * 8, (s + 1) & 1);
            domma(s & 1);
        }

        if (t + 1 < nk) {
            if (t + 2 < nk) { asm volatile("cp.async.wait_group 1;" ::: "memory"); }
            else            { asm volatile("cp.async.wait_group 0;" ::: "memory"); }
            __syncthreads();
        }
    }

    // Epilogue: bias (+ ReLU + tf32-round for kernel1), float2 stores
    #pragma unroll
    for (int i = 0; i < 4; i++) {
        int r0 = bm + wm + i * 16 + grp;
        #pragma unroll
        for (int j = 0; j < 8; j++) {
            int cn = bn + wn + j * 8 + 2 * qid;
            float bv0 = be[cn], bv1 = be[cn + 1];
            float v0 = c[i][j][0] + bv0;
            float v1 = c[i][j][1] + bv1;
            float v2 = c[i][j][2] + bv0;
            float v3 = c[i][j][3] + bv1;
            if (RELU_ROUND) {
                v0 = cvt1(fmaxf(v0, 0.f)); v1 = cvt1(fmaxf(v1, 0.f));
                v2 = cvt1(fmaxf(v2, 0.f)); v3 = cvt1(fmaxf(v3, 0.f));
            }
            *(float2*)&Ce[(size_t)r0 * N + cn]       = make_float2(v0, v1);
            *(float2*)&Ce[(size_t)(r0 + 8) * N + cn] = make_float2(v2, v3);
        }
    }
}

extern "C" void kernel_launch(void* const* d_in, const int* in_sizes, int n_in,
                              void* d_out, int out_size)
{
    const float* x  = (const float*)d_in[0];   // [E, T, D]
    const float* w1 = (const float*)d_in[1];   // [E, D, H]
    const float* b1 = (const float*)d_in[2];   // [E, 1, H]
    const float* w2 = (const float*)d_in[3];   // [E, H, D]
    const float* b2 = (const float*)d_in[4];   // [E, 1, D]
    float* out = (float*)d_out;                // [E, T, D]

    float *hid, *gx, *gw1, *gw2;
    cudaGetSymbolAddress((void**)&hid, g_hidden);
    cudaGetSymbolAddress((void**)&gx,  g_x);
    cudaGetSymbolAddress((void**)&gw1, g_w1);
    cudaGetSymbolAddress((void**)&gw2, g_w2);

    cudaFuncSetAttribute(ffn_gemm<true>,  cudaFuncAttributeMaxDynamicSharedMemorySize, DSMEM_BYTES);
    cudaFuncSetAttribute(ffn_gemm<false>, cudaFuncAttributeMaxDynamicSharedMemorySize, DSMEM_BYTES);

    // Prepass: round operands to the tf32 grid once (idempotent numerics)
    const int nx  = EXPERTS * TOK * DMODEL / 4;
    const int nw1 = EXPERTS * DMODEL * HID / 4;
    const int nw2 = EXPERTS * HID * DMODEL / 4;
    round_tf32<<<1184, 256>>>((const float4*)x,  (float4*)gx,  nx);
    round_tf32<<<1184, 256>>>((const float4*)w1, (float4*)gw1, nw1);
    round_tf32<<<1184, 256>>>((const float4*)w2, (float4*)gw2, nw2);

    dim3 blk(128);
    ffn_gemm<true><<<dim3(HID / BN, TOK / BM, EXPERTS), blk, DSMEM_BYTES>>>(
        gx, gw1, b1, hid, TOK, HID, DMODEL);
    ffn_gemm<false><<<dim3(DMODEL / BN, TOK / BM, EXPERTS), blk, DSMEM_BYTES>>>(
        hid, gw2, b2, out, TOK, DMODEL, HID);
}

// round 7
// speedup vs baseline: 1.0543x; 1.0543x over previous
#include <cuda_runtime.h>
#include <cstdint>
#include <cstddef>

#define EXPERTS 8
#define TOK     2048
#define DMODEL  1024
#define HID     4096

// Static device scratch (no allocations allowed anywhere)
__device__ float g_hidden[(size_t)EXPERTS * TOK * HID];   // tf32-rounded by kernel1
__device__ float g_x [(size_t)EXPERTS * TOK * DMODEL];    // tf32-rounded x
__device__ float g_w1[(size_t)EXPERTS * DMODEL * HID];    // tf32-rounded w1
__device__ float g_w2[(size_t)EXPERTS * HID * DMODEL];    // tf32-rounded w2

// CTA tile 128x128, 128 threads (4 warps 2x2, 64x64 each), BK=16, 4-stage cp.async,
// 3 CTAs/SM (12 warps -> 3 per SMSP)
#define BM 128
#define BN 128
#define BK 16
#define APITCH 20      // frag bank = (20*grp+qid)%32 -> all 32 distinct
#define BPITCH 136     // frag bank = (8*qid+grp)%32  -> all 32 distinct
#define A_FLOATS (BM * APITCH)            // 2560
#define B_FLOATS (BK * BPITCH)            // 2176
#define S_FLOATS (A_FLOATS + B_FLOATS)    // 4736 (18944 B/stage)
#define NSTAGE 4
#define DSMEM_BYTES (NSTAGE * S_FLOATS * 4)   // 75776 B -> 3 CTAs/SM (222KB)

static __device__ __forceinline__ uint32_t smem_u32(const void* p) {
    uint32_t a;
    asm("{ .reg .u64 t; cvta.to.shared.u64 t, %1; cvt.u32.u64 %0, t; }" : "=r"(a) : "l"(p));
    return a;
}
static __device__ __forceinline__ void cp16(void* d, const void* s) {
    asm volatile("cp.async.cg.shared.global [%0], [%1], 16;" :: "r"(smem_u32(d)), "l"(s));
}
static __device__ __forceinline__ float4 cvt4(float4 v) {
    uint4 o;
    asm("cvt.rna.tf32.f32 %0, %1;" : "=r"(o.x) : "f"(v.x));
    asm("cvt.rna.tf32.f32 %0, %1;" : "=r"(o.y) : "f"(v.y));
    asm("cvt.rna.tf32.f32 %0, %1;" : "=r"(o.z) : "f"(v.z));
    asm("cvt.rna.tf32.f32 %0, %1;" : "=r"(o.w) : "f"(v.w));
    float4 r;
    r.x = __uint_as_float(o.x); r.y = __uint_as_float(o.y);
    r.z = __uint_as_float(o.z); r.w = __uint_as_float(o.w);
    return r;
}
static __device__ __forceinline__ float cvt1(float v) {
    uint32_t o;
    asm("cvt.rna.tf32.f32 %0, %1;" : "=r"(o) : "f"(v));
    return __uint_as_float(o);
}

// Elementwise tf32-rounding prepass (grid-stride, float4)
__global__ void round_tf32(const float4* __restrict__ in, float4* __restrict__ out, int n4) {
    for (int i = blockIdx.x * blockDim.x + threadIdx.x; i < n4; i += gridDim.x * blockDim.x)
        out[i] = cvt4(in[i]);
}

// C = relu?(A*B + bias) (+ tf32-round of output for kernel1).
// A[M,K], B[K,N] row-major, PRE-ROUNDED to tf32 grid. Batched over blockIdx.z.
template <bool RELU_ROUND>
__global__ __launch_bounds__(128, 3)
void ffn_gemm(const float* __restrict__ A, const float* __restrict__ B,
              const float* __restrict__ bias, float* __restrict__ C,
              int M, int N, int K)
{
    extern __shared__ __align__(16) float sm[];

    const int e = blockIdx.z;
    const float* Ae = A + (size_t)e * M * K;
    const float* Be = B + (size_t)e * K * N;
    const float* be = bias + (size_t)e * N;
    float*       Ce = C + (size_t)e * M * N;

    const int bm = blockIdx.y * BM;
    const int bn = blockIdx.x * BN;

    const int tid  = threadIdx.x;
    const int warp = tid >> 5;
    const int lane = tid & 31;
    const int wm   = (warp >> 1) * 64;
    const int wn   = (warp & 1) * 64;
    const int grp  = lane >> 2;
    const int qid  = lane & 3;

    float c[4][8][4];
    #pragma unroll
    for (int i = 0; i < 4; i++)
        #pragma unroll
        for (int j = 0; j < 8; j++)
            #pragma unroll
            for (int r = 0; r < 4; r++) c[i][j][r] = 0.f;

    const int nk = K / BK;

    // cp.async loader: A 512 chunks (128 rows x 4), B 512 chunks (16 rows x 32); 4+4/thread
    auto issue = [&](int t) {
        float* As = sm + (t % NSTAGE) * S_FLOATS;
        float* Bs = As + A_FLOATS;
        const int k0 = t * BK;
        #pragma unroll
        for (int i = 0; i < 4; i++) {
            int f = tid + (i << 7);
            int r = f >> 2, ch = (f & 3) << 2;
            cp16(As + r * APITCH + ch, Ae + (size_t)(bm + r) * K + k0 + ch);
        }
        #pragma unroll
        for (int i = 0; i < 4; i++) {
            int f = tid + (i << 7);
            int r = f >> 5, ch = (f & 31) << 2;
            cp16(Bs + r * BPITCH + ch, Be + (size_t)(k0 + r) * N + bn + ch);
        }
        asm volatile("cp.async.commit_group;" ::: "memory");
    };

    // Prologue: stages 0..2 in flight.
    issue(0);
    issue(1);
    issue(2);

    for (int t = 0; t < nk; t++) {
        asm volatile("cp.async.wait_group 2;" ::: "memory");   // stage t landed
        __syncthreads();                                        // all warps done with stage t-1 reads
        if (t + 3 < nk) issue(t + 3);                           // refill stage (t-1)%4

        const float* As = sm + (t % NSTAGE) * S_FLOATS;
        const float* Bs = As + A_FLOATS;

        #pragma unroll
        for (int kk = 0; kk < BK; kk += 8) {
            uint32_t a[4][4], b[8][2];
            #pragma unroll
            for (int i = 0; i < 4; i++) {
                const float* ap = As + (wm + i * 16 + grp) * APITCH + kk + qid;
                a[i][0] = __float_as_uint(ap[0]);
                a[i][1] = __float_as_uint(ap[8 * APITCH]);
                a[i][2] = __float_as_uint(ap[4]);
                a[i][3] = __float_as_uint(ap[8 * APITCH + 4]);
            }
            #pragma unroll
            for (int j = 0; j < 8; j++) {
                const float* bp = Bs + (kk + qid) * BPITCH + wn + j * 8 + grp;
                b[j][0] = __float_as_uint(bp[0]);
                b[j][1] = __float_as_uint(bp[4 * BPITCH]);
            }
            #pragma unroll
            for (int i = 0; i < 4; i++)
                #pragma unroll
                for (int j = 0; j < 8; j++) {
                    asm volatile(
                        "mma.sync.aligned.m16n8k8.row.col.f32.tf32.tf32.f32 "
                        "{%0,%1,%2,%3}, {%4,%5,%6,%7}, {%8,%9}, {%0,%1,%2,%3};"
                        : "+f"(c[i][j][0]), "+f"(c[i][j][1]),
                          "+f"(c[i][j][2]), "+f"(c[i][j][3])
                        : "r"(a[i][0]), "r"(a[i][1]), "r"(a[i][2]), "r"(a[i][3]),
                          "r"(b[j][0]), "r"(b[j][1]));
                }
        }
    }

    // Epilogue: bias (+ ReLU + tf32-round for kernel1), float2 stores
    #pragma unroll
    for (int i = 0; i < 4; i++) {
        int r0 = bm + wm + i * 16 + grp;
        #pragma unroll
        for (int j = 0; j < 8; j++) {
            int cn = bn + wn + j * 8 + 2 * qid;
            float bv0 = be[cn], bv1 = be[cn + 1];
            float v0 = c[i][j][0] + bv0;
            float v1 = c[i][j][1] + bv1;
            float v2 = c[i][j][2] + bv0;
            float v3 = c[i][j][3] + bv1;
            if (RELU_ROUND) {
                v0 = cvt1(fmaxf(v0, 0.f)); v1 = cvt1(fmaxf(v1, 0.f));
                v2 = cvt1(fmaxf(v2, 0.f)); v3 = cvt1(fmaxf(v3, 0.f));
            }
            *(float2*)&Ce[(size_t)r0 * N + cn]       = make_float2(v0, v1);
            *(float2*)&Ce[(size_t)(r0 + 8) * N + cn] = make_float2(v2, v3);
        }
    }
}

extern "C" void kernel_launch(void* const* d_in, const int* in_sizes, int n_in,
                              void* d_out, int out_size)
{
    const float* x  = (const float*)d_in[0];   // [E, T, D]
    const float* w1 = (const float*)d_in[1];   // [E, D, H]
    const float* b1 = (const float*)d_in[2];   // [E, 1, H]
    const float* w2 = (const float*)d_in[3];   // [E, H, D]
    const float* b2 = (const float*)d_in[4];   // [E, 1, D]
    float* out = (float*)d_out;                // [E, T, D]

    float *hid, *gx, *gw1, *gw2;
    cudaGetSymbolAddress((void**)&hid, g_hidden);
    cudaGetSymbolAddress((void**)&gx,  g_x);
    cudaGetSymbolAddress((void**)&gw1, g_w1);
    cudaGetSymbolAddress((void**)&gw2, g_w2);

    cudaFuncSetAttribute(ffn_gemm<true>,  cudaFuncAttributeMaxDynamicSharedMemorySize, DSMEM_BYTES);
    cudaFuncSetAttribute(ffn_gemm<false>, cudaFuncAttributeMaxDynamicSharedMemorySize, DSMEM_BYTES);

    // Prepass: round operands to the tf32 grid once (idempotent numerics)
    const int nx  = EXPERTS * TOK * DMODEL / 4;
    const int nw1 = EXPERTS * DMODEL * HID / 4;
    const int nw2 = EXPERTS * HID * DMODEL / 4;
    round_tf32<<<1184, 256>>>((const float4*)x,  (float4*)gx,  nx);
    round_tf32<<<1184, 256>>>((const float4*)w1, (float4*)gw1, nw1);
    round_tf32<<<1184, 256>>>((const float4*)w2, (float4*)gw2, nw2);

    dim3 blk(128);
    ffn_gemm<true><<<dim3(HID / BN, TOK / BM, EXPERTS), blk, DSMEM_BYTES>>>(
        gx, gw1, b1, hid, TOK, HID, DMODEL);
    ffn_gemm<false><<<dim3(DMODEL / BN, TOK / BM, EXPERTS), blk, DSMEM_BYTES>>>(
        hid, gw2, b2, out, TOK, DMODEL, HID);
}

// round 8
// speedup vs baseline: 1.0611x; 1.0064x over previous
#include <cuda_runtime.h>
#include <cstdint>
#include <cstddef>

#define EXPERTS 8
#define TOK     2048
#define DMODEL  1024
#define HID     4096

// Static device scratch (no allocations allowed anywhere)
__device__ float g_hidden[(size_t)EXPERTS * TOK * HID];   // tf32-rounded by kernel1
__device__ float g_x [(size_t)EXPERTS * TOK * DMODEL];    // tf32-rounded x
__device__ float g_w1[(size_t)EXPERTS * DMODEL * HID];    // tf32-rounded w1
__device__ float g_w2[(size_t)EXPERTS * HID * DMODEL];    // tf32-rounded w2

// CTA tile 128x128, 128 threads (4 warps 2x2, 64x64 each), BK=16, 3-stage cp.async,
// 3 CTAs/SM. A fragments via ldmatrix.x4 (APITCH=28: 112B rows, 16B-aligned,
// ldmatrix banks 28r%32 all distinct). B fragments via scalar LDS (BPITCH=136).
#define BM 128
#define BN 128
#define BK 16
#define APITCH 28
#define BPITCH 136
#define A_FLOATS (BM * APITCH)            // 3584
#define B_FLOATS (BK * BPITCH)            // 2176
#define S_FLOATS (A_FLOATS + B_FLOATS)    // 5760 (23040 B/stage)
#define NSTAGE 3
#define DSMEM_BYTES (NSTAGE * S_FLOATS * 4)   // 69120 B -> 3 CTAs/SM (207KB)

static __device__ __forceinline__ uint32_t smem_u32(const void* p) {
    uint32_t a;
    asm("{ .reg .u64 t; cvta.to.shared.u64 t, %1; cvt.u32.u64 %0, t; }" : "=r"(a) : "l"(p));
    return a;
}
static __device__ __forceinline__ void cp16(void* d, const void* s) {
    asm volatile("cp.async.cg.shared.global [%0], [%1], 16;" :: "r"(smem_u32(d)), "l"(s));
}
static __device__ __forceinline__ float4 cvt4(float4 v) {
    uint4 o;
    asm("cvt.rna.tf32.f32 %0, %1;" : "=r"(o.x) : "f"(v.x));
    asm("cvt.rna.tf32.f32 %0, %1;" : "=r"(o.y) : "f"(v.y));
    asm("cvt.rna.tf32.f32 %0, %1;" : "=r"(o.z) : "f"(v.z));
    asm("cvt.rna.tf32.f32 %0, %1;" : "=r"(o.w) : "f"(v.w));
    float4 r;
    r.x = __uint_as_float(o.x); r.y = __uint_as_float(o.y);
    r.z = __uint_as_float(o.z); r.w = __uint_as_float(o.w);
    return r;
}
static __device__ __forceinline__ float cvt1(float v) {
    uint32_t o;
    asm("cvt.rna.tf32.f32 %0, %1;" : "=r"(o) : "f"(v));
    return __uint_as_float(o);
}

// Elementwise tf32-rounding prepass (grid-stride, float4)
__global__ void round_tf32(const float4* __restrict__ in, float4* __restrict__ out, int n4) {
    for (int i = blockIdx.x * blockDim.x + threadIdx.x; i < n4; i += gridDim.x * blockDim.x)
        out[i] = cvt4(in[i]);
}

// C = relu?(A*B + bias) (+ tf32-round of output for kernel1).
// A[M,K], B[K,N] row-major, PRE-ROUNDED to tf32 grid. Batched over blockIdx.z.
template <bool RELU_ROUND>
__global__ __launch_bounds__(128, 3)
void ffn_gemm(const float* __restrict__ A, const float* __restrict__ B,
              const float* __restrict__ bias, float* __restrict__ C,
              int M, int N, int K)
{
    extern __shared__ __align__(16) float sm[];

    const int e = blockIdx.z;
    const float* Ae = A + (size_t)e * M * K;
    const float* Be = B + (size_t)e * K * N;
    const float* be = bias + (size_t)e * N;
    float*       Ce = C + (size_t)e * M * N;

    const int bm = blockIdx.y * BM;
    const int bn = blockIdx.x * BN;

    const int tid  = threadIdx.x;
    const int warp = tid >> 5;
    const int lane = tid & 31;
    const int wm   = (warp >> 1) * 64;
    const int wn   = (warp & 1) * 64;
    const int grp  = lane >> 2;
    const int qid  = lane & 3;
    // ldmatrix lane -> (row within 16, col-half) mapping for the x4 A load
    const int rowsel = ((lane >> 3) & 1) * 8 + (lane & 7);
    const int colsel = (lane >> 4) << 2;          // 0 or 4

    float c[4][8][4];
    #pragma unroll
    for (int i = 0; i < 4; i++)
        #pragma unroll
        for (int j = 0; j < 8; j++)
            #pragma unroll
            for (int r = 0; r < 4; r++) c[i][j][r] = 0.f;

    const int nk = K / BK;

    // cp.async loader: A 512 chunks (128 rows x 4), B 512 chunks (16 rows x 32); 4+4/thread
    auto issue = [&](int t) {
        float* As = sm + (t % NSTAGE) * S_FLOATS;
        float* Bs = As + A_FLOATS;
        const int k0 = t * BK;
        #pragma unroll
        for (int i = 0; i < 4; i++) {
            int f = tid + (i << 7);
            int r = f >> 2, ch = (f & 3) << 2;
            cp16(As + r * APITCH + ch, Ae + (size_t)(bm + r) * K + k0 + ch);
        }
        #pragma unroll
        for (int i = 0; i < 4; i++) {
            int f = tid + (i << 7);
            int r = f >> 5, ch = (f & 31) << 2;
            cp16(Bs + r * BPITCH + ch, Be + (size_t)(k0 + r) * N + bn + ch);
        }
        asm volatile("cp.async.commit_group;" ::: "memory");
    };

    // Prologue: stages 0..1 in flight.
    issue(0);
    issue(1);

    for (int t = 0; t < nk; t++) {
        if (t + 1 < nk) { asm volatile("cp.async.wait_group 1;" ::: "memory"); }
        else            { asm volatile("cp.async.wait_group 0;" ::: "memory"); }
        __syncthreads();                 // stage t ready; all warps done reading stage t-1
        if (t + 2 < nk) issue(t + 2);    // refill stage (t+2)%3 == (t-1)%3

        const float* As = sm + (t % NSTAGE) * S_FLOATS;
        const float* Bs = As + A_FLOATS;
        const uint32_t sa = smem_u32(As) + ((wm + rowsel) * APITCH + colsel) * 4;

        #pragma unroll
        for (int kk = 0; kk < BK; kk += 8) {
            uint32_t a[4][4], b[8][2];
            #pragma unroll
            for (int i = 0; i < 4; i++) {
                uint32_t addr = sa + (i * 16 * APITCH + kk) * 4;
                asm volatile(
                    "ldmatrix.sync.aligned.m8n8.x4.shared.b16 {%0,%1,%2,%3}, [%4];"
                    : "=r"(a[i][0]), "=r"(a[i][1]), "=r"(a[i][2]), "=r"(a[i][3])
                    : "r"(addr));
            }
            #pragma unroll
            for (int j = 0; j < 8; j++) {
                const float* bp = Bs + (kk + qid) * BPITCH + wn + j * 8 + grp;
                b[j][0] = __float_as_uint(bp[0]);
                b[j][1] = __float_as_uint(bp[4 * BPITCH]);
            }
            #pragma unroll
            for (int i = 0; i < 4; i++)
                #pragma unroll
                for (int j = 0; j < 8; j++) {
                    asm volatile(
                        "mma.sync.aligned.m16n8k8.row.col.f32.tf32.tf32.f32 "
                        "{%0,%1,%2,%3}, {%4,%5,%6,%7}, {%8,%9}, {%0,%1,%2,%3};"
                        : "+f"(c[i][j][0]), "+f"(c[i][j][1]),
                          "+f"(c[i][j][2]), "+f"(c[i][j][3])
                        : "r"(a[i][0]), "r"(a[i][1]), "r"(a[i][2]), "r"(a[i][3]),
                          "r"(b[j][0]), "r"(b[j][1]));
                }
        }
    }

    // Epilogue: bias (+ ReLU + tf32-round for kernel1), float2 stores
    #pragma unroll
    for (int i = 0; i < 4; i++) {
        int r0 = bm + wm + i * 16 + grp;
        #pragma unroll
        for (int j = 0; j < 8; j++) {
            int cn = bn + wn + j * 8 + 2 * qid;
            float bv0 = be[cn], bv1 = be[cn + 1];
            float v0 = c[i][j][0] + bv0;
            float v1 = c[i][j][1] + bv1;
            float v2 = c[i][j][2] + bv0;
            float v3 = c[i][j][3] + bv1;
            if (RELU_ROUND) {
                v0 = cvt1(fmaxf(v0, 0.f)); v1 = cvt1(fmaxf(v1, 0.f));
                v2 = cvt1(fmaxf(v2, 0.f)); v3 = cvt1(fmaxf(v3, 0.f));
            }
            *(float2*)&Ce[(size_t)r0 * N + cn]       = make_float2(v0, v1);
            *(float2*)&Ce[(size_t)(r0 + 8) * N + cn] = make_float2(v2, v3);
        }
    }
}

extern "C" void kernel_launch(void* const* d_in, const int* in_sizes, int n_in,
                              void* d_out, int out_size)
{
    const float* x  = (const float*)d_in[0];   // [E, T, D]
    const float* w1 = (const float*)d_in[1];   // [E, D, H]
    const float* b1 = (const float*)d_in[2];   // [E, 1, H]
    const float* w2 = (const float*)d_in[3];   // [E, H, D]
    const float* b2 = (const float*)d_in[4];   // [E, 1, D]
    float* out = (float*)d_out;                // [E, T, D]

    float *hid, *gx, *gw1, *gw2;
    cudaGetSymbolAddress((void**)&hid, g_hidden);
    cudaGetSymbolAddress((void**)&gx,  g_x);
    cudaGetSymbolAddress((void**)&gw1, g_w1);
    cudaGetSymbolAddress((void**)&gw2, g_w2);

    cudaFuncSetAttribute(ffn_gemm<true>,  cudaFuncAttributeMaxDynamicSharedMemorySize, DSMEM_BYTES);
    cudaFuncSetAttribute(ffn_gemm<false>, cudaFuncAttributeMaxDynamicSharedMemorySize, DSMEM_BYTES);

    // Prepass: round operands to the tf32 grid once (idempotent numerics)
    const int nx  = EXPERTS * TOK * DMODEL / 4;
    const int nw1 = EXPERTS * DMODEL * HID / 4;
    const int nw2 = EXPERTS * HID * DMODEL / 4;
    round_tf32<<<1184, 256>>>((const float4*)x,  (float4*)gx,  nx);
    round_tf32<<<1184, 256>>>((const float4*)w1, (float4*)gw1, nw1);
    round_tf32<<<1184, 256>>>((const float4*)w2, (float4*)gw2, nw2);

    dim3 blk(128);
    ffn_gemm<true><<<dim3(HID / BN, TOK / BM, EXPERTS), blk, DSMEM_BYTES>>>(
        gx, gw1, b1, hid, TOK, HID, DMODEL);
    ffn_gemm<false><<<dim3(DMODEL / BN, TOK / BM, EXPERTS), blk, DSMEM_BYTES>>>(
        hid, gw2, b2, out, TOK, DMODEL, HID);
}

// round 10
// speedup vs baseline: 2.0444x; 1.9267x over previous
#include <cuda_runtime.h>
#include <cuda_fp16.h>
#include <cstdint>
#include <cstddef>

#define EXPERTS 8
#define TOK     2048
#define DMODEL  1024
#define HID     4096

// Static device scratch (no allocations allowed anywhere)
__device__ __half g_hidden[(size_t)EXPERTS * TOK * HID];   // fp16 hidden (written by k1)
__device__ __half g_x [(size_t)EXPERTS * TOK * DMODEL];    // fp16 x
__device__ __half g_w1[(size_t)EXPERTS * DMODEL * HID];    // fp16 w1
__device__ __half g_w2[(size_t)EXPERTS * HID * DMODEL];    // fp16 w2

// CTA tile 128x128, 128 threads (4 warps 2x2, 64x64 each), BK=32 fp16, 4-stage cp.async,
// 3 CTAs/SM. A via ldmatrix.x4 (pitch 80B: 5*16B odd -> conflict-free),
// B via ldmatrix.x4.trans (pitch 272B: 17*16B odd -> conflict-free).
#define BM 128
#define BN 128
#define BK 32
#define APITCH 40      // halves (80 B/row)
#define BPITCH 136     // halves (272 B/row)
#define A_HALVES (BM * APITCH)            // 5120
#define B_HALVES (BK * BPITCH)            // 4352
#define S_HALVES (A_HALVES + B_HALVES)    // 9472 (18944 B/stage)
#define NSTAGE 4
#define DSMEM_BYTES (NSTAGE * S_HALVES * 2)   // 75776 B -> 3 CTAs/SM (222KB)

static __device__ __forceinline__ uint32_t smem_u32(const void* p) {
    uint32_t a;
    asm("{ .reg .u64 t; cvta.to.shared.u64 t, %1; cvt.u32.u64 %0, t; }" : "=r"(a) : "l"(p));
    return a;
}
static __device__ __forceinline__ void cp16(void* d, const void* s) {
    asm volatile("cp.async.cg.shared.global [%0], [%1], 16;" :: "r"(smem_u32(d)), "l"(s));
}

// fp32x4 -> fp16x4 prepass (grid-stride)
__global__ void to_half(const float4* __restrict__ in, __half2* __restrict__ out, int n4) {
    for (int i = blockIdx.x * blockDim.x + threadIdx.x; i < n4; i += gridDim.x * blockDim.x) {
        float4 v = in[i];
        out[2 * i]     = __floats2half2_rn(v.x, v.y);
        out[2 * i + 1] = __floats2half2_rn(v.z, v.w);
    }
}

// C = A[M,K]*B[K,N] + bias.  A,B fp16 row-major.  FIRST: ReLU + fp16 store (hidden);
// else: fp32 store. Batched over blockIdx.z.
template <bool FIRST>
__global__ __launch_bounds__(128, 3)
void ffn_gemm(const __half* __restrict__ A, const __half* __restrict__ B,
              const float* __restrict__ bias, void* __restrict__ Cv,
              int M, int N, int K)
{
    extern __shared__ __align__(16) __half sm[];

    const int e = blockIdx.z;
    const __half* Ae = A + (size_t)e * M * K;
    const __half* Be = B + (size_t)e * K * N;
    const float*  be = bias + (size_t)e * N;

    const int bm = blockIdx.y * BM;
    const int bn = blockIdx.x * BN;

    const int tid  = threadIdx.x;
    const int warp = tid >> 5;
    const int lane = tid & 31;
    const int wm   = (warp >> 1) * 64;
    const int wn   = (warp & 1) * 64;
    const int grp  = lane >> 2;
    const int qid  = lane & 3;
    const int rowsel = ((lane >> 3) & 1) * 8 + (lane & 7);  // row within 16
    const int col8   = (lane >> 4) * 8;                     // 8-half column block

    float c[4][8][4];
    #pragma unroll
    for (int i = 0; i < 4; i++)
        #pragma unroll
        for (int j = 0; j < 8; j++)
            #pragma unroll
            for (int r = 0; r < 4; r++) c[i][j][r] = 0.f;

    const int nk = K / BK;

    // cp.async: A 512 chunks (128 rows x 4x16B), B 512 chunks (32 rows x 16x16B); 4+4/thread
    auto issue = [&](int t) {
        __half* As = sm + (t % NSTAGE) * S_HALVES;
        __half* Bs = As + A_HALVES;
        const int k0 = t * BK;
        #pragma unroll
        for (int i = 0; i < 4; i++) {
            int f = tid + (i << 7);
            int r = f >> 2, ch = (f & 3) << 3;
            cp16(As + r * APITCH + ch, Ae + (size_t)(bm + r) * K + k0 + ch);
        }
        #pragma unroll
        for (int i = 0; i < 4; i++) {
            int f = tid + (i << 7);
            int r = f >> 4, ch = (f & 15) << 3;
            cp16(Bs + r * BPITCH + ch, Be + (size_t)(k0 + r) * N + bn + ch);
        }
        asm volatile("cp.async.commit_group;" ::: "memory");
    };

    // Prologue: stages 0..2 in flight.
    issue(0);
    issue(1);
    issue(2);

    for (int t = 0; t < nk; t++) {
        asm volatile("cp.async.wait_group 2;" ::: "memory");
        __syncthreads();
        if (t + 3 < nk) issue(t + 3);

        const __half* As = sm + (t % NSTAGE) * S_HALVES;
        const __half* Bs = As + A_HALVES;
        const uint32_t abase = smem_u32(As) + (((wm + rowsel) * APITCH) + col8) * 2;
        const uint32_t bbase = smem_u32(Bs) + ((rowsel * BPITCH) + wn + col8) * 2;

        #pragma unroll
        for (int ks = 0; ks < 2; ks++) {
            uint32_t a[4][4];
            #pragma unroll
            for (int i = 0; i < 4; i++) {
                uint32_t addr = abase + (i * 16 * APITCH + ks * 16) * 2;
                asm volatile(
                    "ldmatrix.sync.aligned.m8n8.x4.shared.b16 {%0,%1,%2,%3}, [%4];"
                    : "=r"(a[i][0]), "=r"(a[i][1]), "=r"(a[i][2]), "=r"(a[i][3])
                    : "r"(addr));
            }
            #pragma unroll
            for (int jp = 0; jp < 4; jp++) {
                uint32_t b0, b1, b2, b3;   // n-tiles 2jp (b0,b1) and 2jp+1 (b2,b3)
                uint32_t addr = bbase + (ks * 16 * BPITCH + jp * 16) * 2;
                asm volatile(
                    "ldmatrix.sync.aligned.m8n8.x4.trans.shared.b16 {%0,%1,%2,%3}, [%4];"
                    : "=r"(b0), "=r"(b1), "=r"(b2), "=r"(b3)
                    : "r"(addr));
                #pragma unroll
                for (int i = 0; i < 4; i++) {
                    asm volatile(
                        "mma.sync.aligned.m16n8k16.row.col.f32.f16.f16.f32 "
                        "{%0,%1,%2,%3}, {%4,%5,%6,%7}, {%8,%9}, {%0,%1,%2,%3};"
                        : "+f"(c[i][2*jp][0]), "+f"(c[i][2*jp][1]),
                          "+f"(c[i][2*jp][2]), "+f"(c[i][2*jp][3])
                        : "r"(a[i][0]), "r"(a[i][1]), "r"(a[i][2]), "r"(a[i][3]),
                          "r"(b0), "r"(b1));
                    asm volatile(
                        "mma.sync.aligned.m16n8k16.row.col.f32.f16.f16.f32 "
                        "{%0,%1,%2,%3}, {%4,%5,%6,%7}, {%8,%9}, {%0,%1,%2,%3};"
                        : "+f"(c[i][2*jp+1][0]), "+f"(c[i][2*jp+1][1]),
                          "+f"(c[i][2*jp+1][2]), "+f"(c[i][2*jp+1][3])
                        : "r"(a[i][0]), "r"(a[i][1]), "r"(a[i][2]), "r"(a[i][3]),
                          "r"(b2), "r"(b3));
                }
            }
        }
    }

    // Epilogue
    #pragma unroll
    for (int i = 0; i < 4; i++) {
        int r0 = bm + wm + i * 16 + grp;
        #pragma unroll
        for (int j = 0; j < 8; j++) {
            int cn = bn + wn + j * 8 + 2 * qid;
            float bv0 = be[cn], bv1 = be[cn + 1];
            float v0 = c[i][j][0] + bv0;
            float v1 = c[i][j][1] + bv1;
            float v2 = c[i][j][2] + bv0;
            float v3 = c[i][j][3] + bv1;
            if (FIRST) {
                __half* Ce = (__half*)Cv + (size_t)e * M * N;
                __half2 h01 = __floats2half2_rn(fmaxf(v0, 0.f), fmaxf(v1, 0.f));
                __half2 h23 = __floats2half2_rn(fmaxf(v2, 0.f), fmaxf(v3, 0.f));
                *(__half2*)&Ce[(size_t)r0 * N + cn]       = h01;
                *(__half2*)&Ce[(size_t)(r0 + 8) * N + cn] = h23;
            } else {
                float* Ce = (float*)Cv + (size_t)e * M * N;
                *(float2*)&Ce[(size_t)r0 * N + cn]       = make_float2(v0, v1);
                *(float2*)&Ce[(size_t)(r0 + 8) * N + cn] = make_float2(v2, v3);
            }
        }
    }
}

extern "C" void kernel_launch(void* const* d_in, const int* in_sizes, int n_in,
                              void* d_out, int out_size)
{
    const float* x  = (const float*)d_in[0];   // [E, T, D]
    const float* w1 = (const float*)d_in[1];   // [E, D, H]
    const float* b1 = (const float*)d_in[2];   // [E, 1, H]
    const float* w2 = (const float*)d_in[3];   // [E, H, D]
    const float* b2 = (const float*)d_in[4];   // [E, 1, D]
    float* out = (float*)d_out;                // [E, T, D]

    __half *hid, *gx, *gw1, *gw2;
    cudaGetSymbolAddress((void**)&hid, g_hidden);
    cudaGetSymbolAddress((void**)&gx,  g_x);
    cudaGetSymbolAddress((void**)&gw1, g_w1);
    cudaGetSymbolAddress((void**)&gw2, g_w2);

    cudaFuncSetAttribute(ffn_gemm<true>,  cudaFuncAttributeMaxDynamicSharedMemorySize, DSMEM_BYTES);
    cudaFuncSetAttribute(ffn_gemm<false>, cudaFuncAttributeMaxDynamicSharedMemorySize, DSMEM_BYTES);

    // Prepass: fp32 -> fp16 operands (same 10-bit mantissa rounding class as tf32)
    const int nx  = EXPERTS * TOK * DMODEL / 4;
    const int nw1 = EXPERTS * DMODEL * HID / 4;
    const int nw2 = EXPERTS * HID * DMODEL / 4;
    to_half<<<1184, 256>>>((const float4*)x,  (__half2*)gx,  nx);
    to_half<<<1184, 256>>>((const float4*)w1, (__half2*)gw1, nw1);
    to_half<<<1184, 256>>>((const float4*)w2, (__half2*)gw2, nw2);

    dim3 blk(128);
    ffn_gemm<true><<<dim3(HID / BN, TOK / BM, EXPERTS), blk, DSMEM_BYTES>>>(
        gx, gw1, b1, hid, TOK, HID, DMODEL);
    ffn_gemm<false><<<dim3(DMODEL / BN, TOK / BM, EXPERTS), blk, DSMEM_BYTES>>>(
        hid, gw2, b2, out, TOK, DMODEL, HID);
}